// round 13
// baseline (speedup 1.0000x reference)
#include <cuda_runtime.h>
#include <cuda_fp16.h>
#include <math.h>
#include <stdint.h>

#define Nn 20000
#define Ee 320000
#define Ff 64
#define Hh 256
#define Cc 10
#define Gg 64

// PDL: dependent-launch overlap (sm_90+)
#define PDL_WAIT()    asm volatile("griddepcontrol.wait;" ::: "memory")
#define PDL_TRIGGER() asm volatile("griddepcontrol.launch_dependents;" ::: "memory")

// ---------------- device scratch (static, no allocation) ----------------
// Invariant: g_cnt, g_pool, g_pcnt are zero at entry of every replay
// (zeroed at load; scan re-zeroes g_cnt, out_kernel re-zeroes pool/pcnt).
__device__ __half g_zh[Nn * Hh];         // prescaled GEMM output: dinv_m * z_m (fp16)
__device__ __half g_h[Nn * Hh];          // hidden state (fp16, GEMM input)
__device__ __half g_xs[Nn * Ff];         // prescaled input: dinv_i * x_i (fp16)
__device__ __half g_xh[Nn * Ff];         // aggregated X (fp16, GEMM input)
__device__ __half g_wT[4 * Hh * Hh];     // W2..W5 transposed [m][k] (fp16)
__device__ __half g_w1T[Hh * Ff];        // W1 transposed (fp16)

__device__ float g_dinv[Nn];
__device__ int   g_cnt[Nn];
__device__ int   g_off[Nn + 1];
__device__ int   g_cur[Nn];
__device__ int   g_csr[Ee];
__device__ float g_pool[Gg * Hh];
__device__ int   g_pcnt[Gg];

// ---------------- cp.async helpers ----------------
__device__ __forceinline__ void cp4(uint32_t dst, const void* src) {
    asm volatile("cp.async.ca.shared.global [%0], [%1], 4;" :: "r"(dst), "l"(src));
}
__device__ __forceinline__ void cp16(uint32_t dst, const void* src) {
    asm volatile("cp.async.cg.shared.global [%0], [%1], 16;" :: "r"(dst), "l"(src));
}
__device__ __forceinline__ void cp_commit() { asm volatile("cp.async.commit_group;"); }
template <int NWait>
__device__ __forceinline__ void cp_wait() {
    asm volatile("cp.async.wait_group %0;" :: "n"(NWait));
}

// ---------------- fused prep: degree + graph counts + weight convert ------
__global__ void prep_kernel(const int* __restrict__ edge_index,
                            const int* __restrict__ batch,
                            const float* __restrict__ W1,
                            const float* __restrict__ W2,
                            const float* __restrict__ W3,
                            const float* __restrict__ W4,
                            const float* __restrict__ W5) {
    PDL_WAIT();
    int idx = blockIdx.x * blockDim.x + threadIdx.x;
    if (idx < Ee) {
        atomicAdd(&g_cnt[edge_index[Ee + idx]], 1);
    } else if (idx < Ee + Nn) {
        atomicAdd(&g_pcnt[batch[idx - Ee]], 1);
    } else {
        int w = idx - (Ee + Nn);
        if (w < Ff * Hh) {
            int m = w / Ff, k = w - m * Ff;
            g_w1T[w] = __float2half_rn(W1[k * Hh + m]);
        } else {
            int r = w - Ff * Hh;
            if (r < 4 * Hh * Hh) {
                int widx = r >> 16;
                int loc = r & 65535;
                int m = loc >> 8, k = loc & 255;
                const float* W = (widx == 0) ? W2 : (widx == 1) ? W3
                               : (widx == 2) ? W4 : W5;
                g_wT[r] = __float2half_rn(W[k * Hh + m]);
            }
        }
    }
    PDL_TRIGGER();
}

// ---------------- single-block scan (re-zeroes g_cnt) ----------------
#define SCAN_T 1024
#define SCAN_CH ((Nn + SCAN_T - 1) / SCAN_T)
__global__ void scan_kernel() {
    PDL_WAIT();
    __shared__ int sh[SCAN_T];
    int t = threadIdx.x;
    int base = t * SCAN_CH;
    int s = 0;
    #pragma unroll
    for (int i = 0; i < SCAN_CH; i++) {
        int idx = base + i;
        if (idx < Nn) s += g_cnt[idx];
    }
    sh[t] = s;
    __syncthreads();
    for (int d = 1; d < SCAN_T; d <<= 1) {
        int v = (t >= d) ? sh[t - d] : 0;
        __syncthreads();
        sh[t] += v;
        __syncthreads();
    }
    int run = (t == 0) ? 0 : sh[t - 1];
    for (int i = 0; i < SCAN_CH; i++) {
        int idx = base + i;
        if (idx < Nn) {
            int c = g_cnt[idx];
            g_cnt[idx] = 0;
            g_off[idx] = run;
            g_cur[idx] = run;
            g_dinv[idx] = rsqrtf((float)(c + 1));
            run += c;
        }
    }
    if (t == SCAN_T - 1) g_off[Nn] = sh[SCAN_T - 1];
    PDL_TRIGGER();
}

// ---------------- scatter CSR + prescale x to fp16 ----------------
__global__ void scatter_kernel(const int* __restrict__ edge_index,
                               const float* __restrict__ x) {
    PDL_WAIT();
    int idx = blockIdx.x * blockDim.x + threadIdx.x;
    if (idx < Ee) {
        int r = edge_index[idx];
        int c = edge_index[Ee + idx];
        g_csr[atomicAdd(&g_cur[c], 1)] = r;
    } else {
        int i2 = (idx - Ee) * 2;
        if (i2 < Nn * Ff) {
            int node = i2 >> 6;
            float d = g_dinv[node];
            float2 xv = *(const float2*)(x + i2);
            *(__half2*)(g_xs + i2) = __floats2half2_rn(d * xv.x, d * xv.y);
        }
    }
    PDL_TRIGGER();
}

// ---------------- aggx: warp-per-node, MLP-16, half-tree reduce ----------
// g_xh[i] = dinv_i * ( xs_i + sum_j xs_j )   (xs_k = dinv_k * x_k)
__global__ void aggx_kernel() {
    int warp = threadIdx.x >> 5;
    int lane = threadIdx.x & 31;
    int node = blockIdx.x * 8 + warp;          // 2500 blocks * 8 warps
    PDL_WAIT();
    float di = g_dinv[node];
    const uint32_t* xrow = (const uint32_t*)g_xs;   // 32 uints per 128B row

    float acc0, acc1;
    {
        uint32_t sv = xrow[node * 32 + lane];
        float2 f = __half22float2(*(__half2*)&sv);
        acc0 = f.x; acc1 = f.y;
    }
    int s = g_off[node], e = g_off[node + 1];
    int k = s;
    for (; k + 16 <= e; k += 16) {
        int myj = g_csr[k + (lane & 15)];
        uint32_t v[16];
        #pragma unroll
        for (int u = 0; u < 16; u++) {
            int j = __shfl_sync(0xffffffffu, myj, u);
            v[u] = xrow[j * 32 + lane];
        }
        #pragma unroll
        for (int q = 0; q < 4; q++) {
            __half2 a = __hadd2(*(__half2*)&v[4 * q], *(__half2*)&v[4 * q + 1]);
            __half2 bq = __hadd2(*(__half2*)&v[4 * q + 2], *(__half2*)&v[4 * q + 3]);
            float2 f = __half22float2(__hadd2(a, bq));
            acc0 += f.x; acc1 += f.y;
        }
    }
    for (; k + 4 <= e; k += 4) {
        int myj = g_csr[k + (lane & 3)];
        uint32_t v[4];
        #pragma unroll
        for (int u = 0; u < 4; u++) {
            int j = __shfl_sync(0xffffffffu, myj, u);
            v[u] = xrow[j * 32 + lane];
        }
        __half2 a = __hadd2(*(__half2*)&v[0], *(__half2*)&v[1]);
        __half2 bq = __hadd2(*(__half2*)&v[2], *(__half2*)&v[3]);
        float2 f = __half22float2(__hadd2(a, bq));
        acc0 += f.x; acc1 += f.y;
    }
    for (; k < e; k++) {
        uint32_t v = xrow[g_csr[k] * 32 + lane];
        float2 f = __half22float2(*(__half2*)&v);
        acc0 += f.x; acc1 += f.y;
    }
    *(__half2*)(g_xh + node * Ff + lane * 2) = __floats2half2_rn(di * acc0, di * acc1);
    PDL_TRIGGER();
}

// ---------------- agg (layers 2..5): 4 warps/node, cp.async gather ring ---
// zs prescaled by dinv_j: h[i] = relu( dinv_i*(zs[i] + sum_j zs[j]) + b )
// Each warp owns a 128B quarter-row; gathers stream through a per-warp smem
// ring: 8 edges/group x depth 4 = 32 edges in flight (no register buffers).
#define AG_BATCH 8
#define AG_DEPTH 4
#define AG_WBUF  (AG_BATCH * AG_DEPTH * 128)   // 4KB per warp

template <bool POOL>
__global__ void agg_kernel(const float* __restrict__ b, const int* __restrict__ batch) {
    __shared__ char sbuf[8 * AG_WBUF];         // 32KB (8 warps)
    int warp = threadIdx.x >> 5;
    int lane = threadIdx.x & 31;
    int nw = blockIdx.x * 8 + warp;            // node-warp id, 4*Nn total
    int node = nw >> 2;
    int quart = nw & 3;
    int ucol = quart * 32 + lane;              // uint column 0..127
    uint32_t wbuf = (uint32_t)__cvta_generic_to_shared(sbuf) + warp * AG_WBUF;
    const char* zbase = (const char*)g_zh;     // row j at byte j*512

    PDL_WAIT();
    float di = g_dinv[node];
    const uint32_t* zrow = (const uint32_t*)g_zh;   // 128 uints per 512B row

    float acc0, acc1;
    {
        uint32_t sv = zrow[node * 128 + ucol]; // self term (prescaled)
        float2 f = __half22float2(*(__half2*)&sv);
        acc0 = f.x; acc1 = f.y;
    }

    int s = g_off[node], e = g_off[node + 1];
    int nE = e - s;
    int ngroups = nE / AG_BATCH;
    int srcoff = ucol * 4;                     // byte offset within row

    // issue group g: 8 edges -> ring slots (g % DEPTH)*8 .. +7
    auto issue_group = [&](int g) {
        int kb = s + g * AG_BATCH;
        int myj = g_csr[kb + (lane & 7)];
        uint32_t slot0 = wbuf + (uint32_t)(g & (AG_DEPTH - 1)) * (AG_BATCH * 128);
        #pragma unroll
        for (int u = 0; u < AG_BATCH; u++) {
            int j = __shfl_sync(0xffffffffu, myj, u);
            cp4(slot0 + u * 128 + lane * 4, zbase + (size_t)j * 512 + srcoff);
        }
    };

    // prologue: DEPTH commits (empty groups count and complete immediately)
    #pragma unroll
    for (int g = 0; g < AG_DEPTH; g++) {
        if (g < ngroups) issue_group(g);
        cp_commit();
    }
    // main: consume group g, issue group g+DEPTH, one commit per iteration
    const uint32_t rdbase = wbuf + lane * 4;
    #pragma unroll 1
    for (int g = 0; g < ngroups; g++) {
        cp_wait<AG_DEPTH - 1>();
        uint32_t slot0 = rdbase + (uint32_t)(g & (AG_DEPTH - 1)) * (AG_BATCH * 128);
        #pragma unroll
        for (int u = 0; u < AG_BATCH; u++) {
            uint32_t v;
            asm volatile("ld.shared.u32 %0, [%1];" : "=r"(v) : "r"(slot0 + u * 128));
            float2 f = __half22float2(*(__half2*)&v);
            acc0 += f.x; acc1 += f.y;
        }
        if (g + AG_DEPTH < ngroups) issue_group(g + AG_DEPTH);
        cp_commit();
    }
    cp_wait<0>();

    // tail (< 8 edges): direct loads
    for (int k = s + ngroups * AG_BATCH; k < e; k++) {
        uint32_t v = zrow[g_csr[k] * 128 + ucol];
        float2 f = __half22float2(*(__half2*)&v);
        acc0 += f.x; acc1 += f.y;
    }

    const float2 bb = ((const float2*)b)[ucol];
    float r0 = fmaxf(fmaf(di, acc0, bb.x), 0.0f);
    float r1 = fmaxf(fmaf(di, acc1, bb.y), 0.0f);

    if (POOL) {
        int gph = batch[node];
        float* p = g_pool + gph * Hh + ucol * 2;
        atomicAdd(p + 0, r0);
        atomicAdd(p + 1, r1);
    } else {
        *(__half2*)(g_h + node * Hh + ucol * 2) = __floats2half2_rn(r0, r1);
    }
    PDL_TRIGGER();
}

// ---------------- single-term fp16 tensor-core GEMM ----------------
#define MMA16816(d, a, b)                                                     \
    asm volatile(                                                             \
        "mma.sync.aligned.m16n8k16.row.col.f32.f16.f16.f32 "                  \
        "{%0,%1,%2,%3},{%4,%5,%6,%7},{%8,%9},{%0,%1,%2,%3};"                  \
        : "+f"(d[0]), "+f"(d[1]), "+f"(d[2]), "+f"(d[3])                      \
        : "r"(a[0]), "r"(a[1]), "r"(a[2]), "r"(a[3]), "r"(b[0]), "r"(b[1]))

#define TILE_H 5120
#define BUF_H  (2 * TILE_H)
#define GSMEM_BYTES (2 * BUF_H * 2)   // 40960

template <int K, bool RELU>
__global__ __launch_bounds__(256, 2) void gemm_kernel(int widx, const float* __restrict__ bias) {
    const __half* __restrict__ A = (K == Ff) ? g_xh : g_h;
    const __half* __restrict__ B = (K == Ff) ? g_w1T : g_wT + widx * (Hh * Hh);

    extern __shared__ __half sh[];
    const uint32_t sh32 = (uint32_t)__cvta_generic_to_shared(sh);

    const int tid = threadIdx.x;
    const int warp = tid >> 5;
    const int lane = tid & 31;
    const int g = lane >> 2;
    const int t = lane & 3;
    const int wm = warp >> 2;
    const int wn = warp & 3;
    const int rowbase = blockIdx.y * 128;
    const int colbase = blockIdx.x * 128;

    const int lrow = tid >> 1;
    const int lch = tid & 1;
    int arow = rowbase + lrow;
    if (arow > Nn - 1) arow = Nn - 1;
    const __half* pA = A + arow * K + lch * 16;
    const __half* pB = B + (colbase + lrow) * K + lch * 16;
    const uint32_t sidx_b = (uint32_t)(lrow * 40 + lch * 16) * 2;

    float acc[4][4][4];
    #pragma unroll
    for (int a = 0; a < 4; a++)
        #pragma unroll
        for (int bq = 0; bq < 4; bq++)
            #pragma unroll
            for (int c = 0; c < 4; c++) acc[a][bq][c] = 0.0f;

    const int NT = K / 32;

    auto issue = [&](int kt, int buf) {
        int k0 = kt * 32;
        uint32_t base = sh32 + (uint32_t)buf * (BUF_H * 2) + sidx_b;
        cp16(base,                   pA + k0);
        cp16(base + 16,              pA + k0 + 8);
        cp16(base + TILE_H * 2,      pB + k0);
        cp16(base + TILE_H * 2 + 16, pB + k0 + 8);
    };

    PDL_WAIT();          // operands written by predecessor kernel
    issue(0, 0);
    cp_commit();

    #pragma unroll 1
    for (int kt = 0; kt < NT; kt++) {
        int buf = kt & 1;
        if (kt + 1 < NT) {
            issue(kt + 1, buf ^ 1);
            cp_commit();
            cp_wait<1>();
        } else {
            cp_wait<0>();
        }
        __syncthreads();

        const __half* sA = sh + buf * BUF_H;
        const __half* sB = sA + TILE_H;

        #pragma unroll
        for (int kh = 0; kh < 32; kh += 16) {
            uint32_t Af[4][4], Bf[4][2];
            #pragma unroll
            for (int im = 0; im < 4; im++) {
                int mb = (wm * 64 + im * 16 + g) * 40 + kh + 2 * t;
                Af[im][0] = *(const uint32_t*)&sA[mb];
                Af[im][1] = *(const uint32_t*)&sA[mb + 8 * 40];
                Af[im][2] = *(const uint32_t*)&sA[mb + 8];
                Af[im][3] = *(const uint32_t*)&sA[mb + 8 * 40 + 8];
            }
            #pragma unroll
            for (int in = 0; in < 4; in++) {
                int nb = (wn * 32 + in * 8 + g) * 40 + kh + 2 * t;
                Bf[in][0] = *(const uint32_t*)&sB[nb];
                Bf[in][1] = *(const uint32_t*)&sB[nb + 8];
            }
            #pragma unroll
            for (int im = 0; im < 4; im++)
                #pragma unroll
                for (int in = 0; in < 4; in++)
                    MMA16816(acc[im][in], Af[im], Bf[in]);
        }
        __syncthreads();
    }

    // epilogue
    #pragma unroll
    for (int im = 0; im < 4; im++) {
        int m0 = rowbase + wm * 64 + im * 16 + g;
        float dm0 = (m0 < Nn) ? g_dinv[m0] : 0.0f;
        float dm1 = (m0 + 8 < Nn) ? g_dinv[m0 + 8] : 0.0f;
        #pragma unroll
        for (int in = 0; in < 4; in++) {
            int n = colbase + wn * 32 + in * 8 + 2 * t;
            float c0 = acc[im][in][0], c1 = acc[im][in][1];
            float c2 = acc[im][in][2], c3 = acc[im][in][3];
            if (RELU) {
                float bb0 = bias[n], bb1 = bias[n + 1];
                if (m0 < Nn)
                    *(__half2*)(g_h + m0 * Hh + n) =
                        __floats2half2_rn(fmaxf(c0 + bb0, 0.0f), fmaxf(c1 + bb1, 0.0f));
                if (m0 + 8 < Nn)
                    *(__half2*)(g_h + (m0 + 8) * Hh + n) =
                        __floats2half2_rn(fmaxf(c2 + bb0, 0.0f), fmaxf(c3 + bb1, 0.0f));
            } else {
                // write prescaled fp16: zs[m] = dinv[m] * z[m]
                if (m0 < Nn)
                    *(__half2*)(g_zh + m0 * Hh + n) = __floats2half2_rn(dm0 * c0, dm0 * c1);
                if (m0 + 8 < Nn)
                    *(__half2*)(g_zh + (m0 + 8) * Hh + n) = __floats2half2_rn(dm1 * c2, dm1 * c3);
            }
        }
    }
    PDL_TRIGGER();
}

// ---------------- output head (+ state cleanup for next replay) ----------
__global__ void out_kernel(const float* __restrict__ Wout,
                           const float* __restrict__ bout,
                           float* __restrict__ out) {
    PDL_WAIT();
    __shared__ float sh[Hh];
    int g = blockIdx.x;
    int f = threadIdx.x;
    int c = g_pcnt[g];
    float inv = 1.0f / fmaxf((float)c, 1.0f);
    sh[f] = g_pool[g * Hh + f] * inv;
    g_pool[g * Hh + f] = 0.0f;
    if (f == 0) g_pcnt[g] = 0;
    __syncthreads();
    if (f < Cc) {
        float a = bout[f];
        for (int k = 0; k < Hh; k++)
            a = fmaf(sh[k], Wout[k * Cc + f], a);
        out[g * Cc + f] = a;
    }
    PDL_TRIGGER();
}

// ---------------- PDL launcher ----------------
template <typename F, typename... Args>
static void pdl_launch(F kern, dim3 grid, dim3 block, size_t smem, Args... args) {
    cudaLaunchConfig_t cfg = {};
    cfg.gridDim = grid;
    cfg.blockDim = block;
    cfg.dynamicSmemBytes = smem;
    cfg.stream = 0;
    cudaLaunchAttribute at[1];
    at[0].id = cudaLaunchAttributeProgrammaticStreamSerialization;
    at[0].val.programmaticStreamSerializationAllowed = 1;
    cfg.attrs = at;
    cfg.numAttrs = 1;
    cudaLaunchKernelEx(&cfg, kern, args...);
}

// ---------------- launch ----------------
extern "C" void kernel_launch(void* const* d_in, const int* in_sizes, int n_in,
                              void* d_out, int out_size) {
    const float* x     = (const float*)d_in[0];
    const int*   ei    = (const int*)d_in[1];
    const int*   batch = (const int*)d_in[2];
    const float* W1 = (const float*)d_in[3];
    const float* b1 = (const float*)d_in[4];
    const float* W2 = (const float*)d_in[5];
    const float* b2 = (const float*)d_in[6];
    const float* W3 = (const float*)d_in[7];
    const float* b3 = (const float*)d_in[8];
    const float* W4 = (const float*)d_in[9];
    const float* b4 = (const float*)d_in[10];
    const float* W5 = (const float*)d_in[11];
    const float* b5 = (const float*)d_in[12];
    const float* Wout = (const float*)d_in[13];
    const float* bout = (const float*)d_in[14];
    float* out = (float*)d_out;

    static bool attr_set = false;
    if (!attr_set) {
        cudaFuncSetAttribute(gemm_kernel<Ff, true>,
                             cudaFuncAttributeMaxDynamicSharedMemorySize, GSMEM_BYTES);
        cudaFuncSetAttribute(gemm_kernel<Hh, false>,
                             cudaFuncAttributeMaxDynamicSharedMemorySize, GSMEM_BYTES);
        attr_set = true;
    }

    const int PREP_N = Ee + Nn + Ff * Hh + 4 * Hh * Hh;
    const int SCAT_N = Ee + (Nn * Ff) / 2;
    dim3 ggrid(Hh / 128, (Nn + 127) / 128);   // (2, 157)

    pdl_launch(prep_kernel, dim3((PREP_N + 255) / 256), dim3(256), 0,
               ei, batch, W1, W2, W3, W4, W5);
    pdl_launch(scan_kernel, dim3(1), dim3(SCAN_T), 0);
    pdl_launch(scatter_kernel, dim3((SCAT_N + 255) / 256), dim3(256), 0, ei, x);

    // layer 1: aggregate x first (A(XW) = (AX)W), then GEMM with bias+relu
    pdl_launch(aggx_kernel, dim3(Nn / 8), dim3(256), 0);
    pdl_launch(gemm_kernel<Ff, true>, ggrid, dim3(256), (size_t)GSMEM_BYTES, 0, b1);

    // layers 2..5  (agg uses 4 warps/node -> Nn/2 blocks)
    pdl_launch(gemm_kernel<Hh, false>, ggrid, dim3(256), (size_t)GSMEM_BYTES, 0, (const float*)nullptr);
    pdl_launch(agg_kernel<false>, dim3(Nn / 2), dim3(256), 0, b2, batch);
    pdl_launch(gemm_kernel<Hh, false>, ggrid, dim3(256), (size_t)GSMEM_BYTES, 1, (const float*)nullptr);
    pdl_launch(agg_kernel<false>, dim3(Nn / 2), dim3(256), 0, b3, batch);
    pdl_launch(gemm_kernel<Hh, false>, ggrid, dim3(256), (size_t)GSMEM_BYTES, 2, (const float*)nullptr);
    pdl_launch(agg_kernel<false>, dim3(Nn / 2), dim3(256), 0, b4, batch);
    pdl_launch(gemm_kernel<Hh, false>, ggrid, dim3(256), (size_t)GSMEM_BYTES, 3, (const float*)nullptr);
    pdl_launch(agg_kernel<true>, dim3(Nn / 2), dim3(256), 0, b5, batch);   // fused pool

    pdl_launch(out_kernel, dim3(Gg), dim3(256), 0, Wout, bout, out);
}

// round 14
// speedup vs baseline: 1.1625x; 1.1625x over previous
#include <cuda_runtime.h>
#include <cuda_fp16.h>
#include <math.h>
#include <stdint.h>

#define Nn 20000
#define Ee 320000
#define Ff 64
#define Hh 256
#define Cc 10
#define Gg 64

// PDL: dependent-launch overlap (sm_90+)
#define PDL_WAIT()    asm volatile("griddepcontrol.wait;" ::: "memory")
#define PDL_TRIGGER() asm volatile("griddepcontrol.launch_dependents;" ::: "memory")

// ---------------- device scratch (static, no allocation) ----------------
// Invariant: g_cnt, g_pool, g_pcnt are zero at entry of every replay
// (zeroed at load; scan re-zeroes g_cnt, out_kernel re-zeroes pool/pcnt).
__device__ __half g_zh[Nn * Hh];         // prescaled GEMM output: dinv_m * z_m (fp16)
__device__ __half g_h[Nn * Hh];          // hidden state (fp16, GEMM input)
__device__ __half g_xs[Nn * Ff];         // prescaled input: dinv_i * x_i (fp16)
__device__ __half g_xh[Nn * Ff];         // aggregated X (fp16, GEMM input)
__device__ __half g_wT[4 * Hh * Hh];     // W2..W5 transposed [m][k] (fp16)
__device__ __half g_w1T[Hh * Ff];        // W1 transposed (fp16)

__device__ float g_dinv[Nn];
__device__ int   g_cnt[Nn];
__device__ int   g_off[Nn + 1];
__device__ int   g_cur[Nn];
__device__ int   g_csr[Ee];
__device__ float g_pool[Gg * Hh];
__device__ int   g_pcnt[Gg];

// ---------------- cp.async helpers ----------------
__device__ __forceinline__ void cp16(uint32_t dst, const void* src) {
    asm volatile("cp.async.cg.shared.global [%0], [%1], 16;" :: "r"(dst), "l"(src));
}
__device__ __forceinline__ void cp_commit() { asm volatile("cp.async.commit_group;"); }
template <int NWait>
__device__ __forceinline__ void cp_wait() {
    asm volatile("cp.async.wait_group %0;" :: "n"(NWait));
}

// ---------------- fused prep: degree + graph counts + weight convert ------
__global__ void prep_kernel(const int* __restrict__ edge_index,
                            const int* __restrict__ batch,
                            const float* __restrict__ W1,
                            const float* __restrict__ W2,
                            const float* __restrict__ W3,
                            const float* __restrict__ W4,
                            const float* __restrict__ W5) {
    PDL_WAIT();
    int idx = blockIdx.x * blockDim.x + threadIdx.x;
    if (idx < Ee) {
        atomicAdd(&g_cnt[edge_index[Ee + idx]], 1);
    } else if (idx < Ee + Nn) {
        atomicAdd(&g_pcnt[batch[idx - Ee]], 1);
    } else {
        int w = idx - (Ee + Nn);
        if (w < Ff * Hh) {
            int m = w / Ff, k = w - m * Ff;
            g_w1T[w] = __float2half_rn(W1[k * Hh + m]);
        } else {
            int r = w - Ff * Hh;
            if (r < 4 * Hh * Hh) {
                int widx = r >> 16;
                int loc = r & 65535;
                int m = loc >> 8, k = loc & 255;
                const float* W = (widx == 0) ? W2 : (widx == 1) ? W3
                               : (widx == 2) ? W4 : W5;
                g_wT[r] = __float2half_rn(W[k * Hh + m]);
            }
        }
    }
    PDL_TRIGGER();
}

// ---------------- single-block scan (re-zeroes g_cnt) ----------------
#define SCAN_T 1024
#define SCAN_CH ((Nn + SCAN_T - 1) / SCAN_T)
__global__ void scan_kernel() {
    PDL_WAIT();
    __shared__ int sh[SCAN_T];
    int t = threadIdx.x;
    int base = t * SCAN_CH;
    int s = 0;
    #pragma unroll
    for (int i = 0; i < SCAN_CH; i++) {
        int idx = base + i;
        if (idx < Nn) s += g_cnt[idx];
    }
    sh[t] = s;
    __syncthreads();
    for (int d = 1; d < SCAN_T; d <<= 1) {
        int v = (t >= d) ? sh[t - d] : 0;
        __syncthreads();
        sh[t] += v;
        __syncthreads();
    }
    int run = (t == 0) ? 0 : sh[t - 1];
    for (int i = 0; i < SCAN_CH; i++) {
        int idx = base + i;
        if (idx < Nn) {
            int c = g_cnt[idx];
            g_cnt[idx] = 0;
            g_off[idx] = run;
            g_cur[idx] = run;
            g_dinv[idx] = rsqrtf((float)(c + 1));
            run += c;
        }
    }
    if (t == SCAN_T - 1) g_off[Nn] = sh[SCAN_T - 1];
    PDL_TRIGGER();
}

// ---------------- scatter CSR + prescale x to fp16 ----------------
__global__ void scatter_kernel(const int* __restrict__ edge_index,
                               const float* __restrict__ x) {
    PDL_WAIT();
    int idx = blockIdx.x * blockDim.x + threadIdx.x;
    if (idx < Ee) {
        int r = edge_index[idx];
        int c = edge_index[Ee + idx];
        g_csr[atomicAdd(&g_cur[c], 1)] = r;
    } else {
        int i2 = (idx - Ee) * 2;
        if (i2 < Nn * Ff) {
            int node = i2 >> 6;
            float d = g_dinv[node];
            float2 xv = *(const float2*)(x + i2);
            *(__half2*)(g_xs + i2) = __floats2half2_rn(d * xv.x, d * xv.y);
        }
    }
    PDL_TRIGGER();
}

// ---------------- aggx: warp-per-node, MLP-16, half-tree reduce ----------
// g_xh[i] = dinv_i * ( xs_i + sum_j xs_j )   (xs_k = dinv_k * x_k)
__global__ void aggx_kernel() {
    int warp = threadIdx.x >> 5;
    int lane = threadIdx.x & 31;
    int node = blockIdx.x * 8 + warp;          // 2500 blocks * 8 warps
    PDL_WAIT();
    float di = g_dinv[node];
    const uint32_t* xrow = (const uint32_t*)g_xs;   // 32 uints per 128B row

    float acc0, acc1;
    {
        uint32_t sv = xrow[node * 32 + lane];
        float2 f = __half22float2(*(__half2*)&sv);
        acc0 = f.x; acc1 = f.y;
    }
    int s = g_off[node], e = g_off[node + 1];
    int k = s;
    for (; k + 16 <= e; k += 16) {
        int myj = g_csr[k + (lane & 15)];
        uint32_t v[16];
        #pragma unroll
        for (int u = 0; u < 16; u++) {
            int j = __shfl_sync(0xffffffffu, myj, u);
            v[u] = xrow[j * 32 + lane];
        }
        #pragma unroll
        for (int q = 0; q < 4; q++) {
            __half2 a = __hadd2(*(__half2*)&v[4 * q], *(__half2*)&v[4 * q + 1]);
            __half2 bq = __hadd2(*(__half2*)&v[4 * q + 2], *(__half2*)&v[4 * q + 3]);
            float2 f = __half22float2(__hadd2(a, bq));
            acc0 += f.x; acc1 += f.y;
        }
    }
    for (; k + 4 <= e; k += 4) {
        int myj = g_csr[k + (lane & 3)];
        uint32_t v[4];
        #pragma unroll
        for (int u = 0; u < 4; u++) {
            int j = __shfl_sync(0xffffffffu, myj, u);
            v[u] = xrow[j * 32 + lane];
        }
        __half2 a = __hadd2(*(__half2*)&v[0], *(__half2*)&v[1]);
        __half2 bq = __hadd2(*(__half2*)&v[2], *(__half2*)&v[3]);
        float2 f = __half22float2(__hadd2(a, bq));
        acc0 += f.x; acc1 += f.y;
    }
    for (; k < e; k++) {
        uint32_t v = xrow[g_csr[k] * 32 + lane];
        float2 f = __half22float2(*(__half2*)&v);
        acc0 += f.x; acc1 += f.y;
    }
    *(__half2*)(g_xh + node * Ff + lane * 2) = __floats2half2_rn(di * acc0, di * acc1);
    PDL_TRIGGER();
}

// ---------------- agg (layers 2..5): 4 warps/node, MLP-8, half-tree -------
// zs prescaled by dinv_j: h[i] = relu( dinv_i*(zs[i] + sum_j zs[j]) + b )
// Each warp owns a 128B quarter-row: 32 lanes x uint (4B = half2).
template <bool POOL>
__global__ void agg_kernel(const float* __restrict__ b, const int* __restrict__ batch) {
    int warp = threadIdx.x >> 5;
    int lane = threadIdx.x & 31;
    int nw = blockIdx.x * 8 + warp;            // node-warp id, 4*Nn total
    int node = nw >> 2;
    int quart = nw & 3;
    int ucol = quart * 32 + lane;              // uint column 0..127
    PDL_WAIT();
    float di = g_dinv[node];
    const uint32_t* zrow = (const uint32_t*)g_zh;   // 128 uints per 512B row

    float acc0, acc1;
    {
        uint32_t sv = zrow[node * 128 + ucol]; // self term (prescaled)
        float2 f = __half22float2(*(__half2*)&sv);
        acc0 = f.x; acc1 = f.y;
    }

    int s = g_off[node], e = g_off[node + 1];
    int k = s;
    for (; k + 8 <= e; k += 8) {
        int myj = g_csr[k + (lane & 7)];
        uint32_t v[8];
        #pragma unroll
        for (int u = 0; u < 8; u++) {
            int j = __shfl_sync(0xffffffffu, myj, u);
            v[u] = zrow[j * 128 + ucol];
        }
        // half-tree reduce: 2 groups of 4 (fp16 pairwise, fp32 accumulate)
        #pragma unroll
        for (int q = 0; q < 2; q++) {
            __half2 a  = __hadd2(*(__half2*)&v[4 * q],     *(__half2*)&v[4 * q + 1]);
            __half2 bq = __hadd2(*(__half2*)&v[4 * q + 2], *(__half2*)&v[4 * q + 3]);
            float2 f = __half22float2(__hadd2(a, bq));
            acc0 += f.x; acc1 += f.y;
        }
    }
    for (; k + 4 <= e; k += 4) {
        int myj = g_csr[k + (lane & 3)];
        uint32_t v[4];
        #pragma unroll
        for (int u = 0; u < 4; u++) {
            int j = __shfl_sync(0xffffffffu, myj, u);
            v[u] = zrow[j * 128 + ucol];
        }
        __half2 a  = __hadd2(*(__half2*)&v[0], *(__half2*)&v[1]);
        __half2 bq = __hadd2(*(__half2*)&v[2], *(__half2*)&v[3]);
        float2 f = __half22float2(__hadd2(a, bq));
        acc0 += f.x; acc1 += f.y;
    }
    for (; k < e; k++) {
        uint32_t v = zrow[g_csr[k] * 128 + ucol];
        float2 f = __half22float2(*(__half2*)&v);
        acc0 += f.x; acc1 += f.y;
    }

    const float2 bb = ((const float2*)b)[ucol];
    float r0 = fmaxf(fmaf(di, acc0, bb.x), 0.0f);
    float r1 = fmaxf(fmaf(di, acc1, bb.y), 0.0f);

    if (POOL) {
        int gph = batch[node];
        float* p = g_pool + gph * Hh + ucol * 2;
        atomicAdd(p + 0, r0);
        atomicAdd(p + 1, r1);
    } else {
        *(__half2*)(g_h + node * Hh + ucol * 2) = __floats2half2_rn(r0, r1);
    }
    PDL_TRIGGER();
}

// ---------------- single-term fp16 tensor-core GEMM ----------------
#define MMA16816(d, a, b)                                                     \
    asm volatile(                                                             \
        "mma.sync.aligned.m16n8k16.row.col.f32.f16.f16.f32 "                  \
        "{%0,%1,%2,%3},{%4,%5,%6,%7},{%8,%9},{%0,%1,%2,%3};"                  \
        : "+f"(d[0]), "+f"(d[1]), "+f"(d[2]), "+f"(d[3])                      \
        : "r"(a[0]), "r"(a[1]), "r"(a[2]), "r"(a[3]), "r"(b[0]), "r"(b[1]))

#define TILE_H 5120
#define BUF_H  (2 * TILE_H)
#define GSMEM_BYTES (2 * BUF_H * 2)   // 40960

template <int K, bool RELU>
__global__ __launch_bounds__(256, 2) void gemm_kernel(int widx, const float* __restrict__ bias) {
    const __half* __restrict__ A = (K == Ff) ? g_xh : g_h;
    const __half* __restrict__ B = (K == Ff) ? g_w1T : g_wT + widx * (Hh * Hh);

    extern __shared__ __half sh[];
    const uint32_t sh32 = (uint32_t)__cvta_generic_to_shared(sh);

    const int tid = threadIdx.x;
    const int warp = tid >> 5;
    const int lane = tid & 31;
    const int g = lane >> 2;
    const int t = lane & 3;
    const int wm = warp >> 2;
    const int wn = warp & 3;
    const int rowbase = blockIdx.y * 128;
    const int colbase = blockIdx.x * 128;

    const int lrow = tid >> 1;
    const int lch = tid & 1;
    int arow = rowbase + lrow;
    if (arow > Nn - 1) arow = Nn - 1;
    const __half* pA = A + arow * K + lch * 16;
    const __half* pB = B + (colbase + lrow) * K + lch * 16;
    const uint32_t sidx_b = (uint32_t)(lrow * 40 + lch * 16) * 2;

    float acc[4][4][4];
    #pragma unroll
    for (int a = 0; a < 4; a++)
        #pragma unroll
        for (int bq = 0; bq < 4; bq++)
            #pragma unroll
            for (int c = 0; c < 4; c++) acc[a][bq][c] = 0.0f;

    const int NT = K / 32;

    auto issue = [&](int kt, int buf) {
        int k0 = kt * 32;
        uint32_t base = sh32 + (uint32_t)buf * (BUF_H * 2) + sidx_b;
        cp16(base,                   pA + k0);
        cp16(base + 16,              pA + k0 + 8);
        cp16(base + TILE_H * 2,      pB + k0);
        cp16(base + TILE_H * 2 + 16, pB + k0 + 8);
    };

    PDL_WAIT();          // operands written by predecessor kernel
    issue(0, 0);
    cp_commit();

    #pragma unroll 1
    for (int kt = 0; kt < NT; kt++) {
        int buf = kt & 1;
        if (kt + 1 < NT) {
            issue(kt + 1, buf ^ 1);
            cp_commit();
            cp_wait<1>();
        } else {
            cp_wait<0>();
        }
        __syncthreads();

        const __half* sA = sh + buf * BUF_H;
        const __half* sB = sA + TILE_H;

        #pragma unroll
        for (int kh = 0; kh < 32; kh += 16) {
            uint32_t Af[4][4], Bf[4][2];
            #pragma unroll
            for (int im = 0; im < 4; im++) {
                int mb = (wm * 64 + im * 16 + g) * 40 + kh + 2 * t;
                Af[im][0] = *(const uint32_t*)&sA[mb];
                Af[im][1] = *(const uint32_t*)&sA[mb + 8 * 40];
                Af[im][2] = *(const uint32_t*)&sA[mb + 8];
                Af[im][3] = *(const uint32_t*)&sA[mb + 8 * 40 + 8];
            }
            #pragma unroll
            for (int in = 0; in < 4; in++) {
                int nb = (wn * 32 + in * 8 + g) * 40 + kh + 2 * t;
                Bf[in][0] = *(const uint32_t*)&sB[nb];
                Bf[in][1] = *(const uint32_t*)&sB[nb + 8];
            }
            #pragma unroll
            for (int im = 0; im < 4; im++)
                #pragma unroll
                for (int in = 0; in < 4; in++)
                    MMA16816(acc[im][in], Af[im], Bf[in]);
        }
        __syncthreads();
    }

    // epilogue
    #pragma unroll
    for (int im = 0; im < 4; im++) {
        int m0 = rowbase + wm * 64 + im * 16 + g;
        float dm0 = (m0 < Nn) ? g_dinv[m0] : 0.0f;
        float dm1 = (m0 + 8 < Nn) ? g_dinv[m0 + 8] : 0.0f;
        #pragma unroll
        for (int in = 0; in < 4; in++) {
            int n = colbase + wn * 32 + in * 8 + 2 * t;
            float c0 = acc[im][in][0], c1 = acc[im][in][1];
            float c2 = acc[im][in][2], c3 = acc[im][in][3];
            if (RELU) {
                float bb0 = bias[n], bb1 = bias[n + 1];
                if (m0 < Nn)
                    *(__half2*)(g_h + m0 * Hh + n) =
                        __floats2half2_rn(fmaxf(c0 + bb0, 0.0f), fmaxf(c1 + bb1, 0.0f));
                if (m0 + 8 < Nn)
                    *(__half2*)(g_h + (m0 + 8) * Hh + n) =
                        __floats2half2_rn(fmaxf(c2 + bb0, 0.0f), fmaxf(c3 + bb1, 0.0f));
            } else {
                // write prescaled fp16: zs[m] = dinv[m] * z[m]
                if (m0 < Nn)
                    *(__half2*)(g_zh + m0 * Hh + n) = __floats2half2_rn(dm0 * c0, dm0 * c1);
                if (m0 + 8 < Nn)
                    *(__half2*)(g_zh + (m0 + 8) * Hh + n) = __floats2half2_rn(dm1 * c2, dm1 * c3);
            }
        }
    }
    PDL_TRIGGER();
}

// ---------------- output head (+ state cleanup for next replay) ----------
__global__ void out_kernel(const float* __restrict__ Wout,
                           const float* __restrict__ bout,
                           float* __restrict__ out) {
    PDL_WAIT();
    __shared__ float sh[Hh];
    int g = blockIdx.x;
    int f = threadIdx.x;
    int c = g_pcnt[g];
    float inv = 1.0f / fmaxf((float)c, 1.0f);
    sh[f] = g_pool[g * Hh + f] * inv;
    g_pool[g * Hh + f] = 0.0f;
    if (f == 0) g_pcnt[g] = 0;
    __syncthreads();
    if (f < Cc) {
        float a = bout[f];
        for (int k = 0; k < Hh; k++)
            a = fmaf(sh[k], Wout[k * Cc + f], a);
        out[g * Cc + f] = a;
    }
    PDL_TRIGGER();
}

// ---------------- PDL launcher ----------------
template <typename F, typename... Args>
static void pdl_launch(F kern, dim3 grid, dim3 block, size_t smem, Args... args) {
    cudaLaunchConfig_t cfg = {};
    cfg.gridDim = grid;
    cfg.blockDim = block;
    cfg.dynamicSmemBytes = smem;
    cfg.stream = 0;
    cudaLaunchAttribute at[1];
    at[0].id = cudaLaunchAttributeProgrammaticStreamSerialization;
    at[0].val.programmaticStreamSerializationAllowed = 1;
    cfg.attrs = at;
    cfg.numAttrs = 1;
    cudaLaunchKernelEx(&cfg, kern, args...);
}

// ---------------- launch ----------------
extern "C" void kernel_launch(void* const* d_in, const int* in_sizes, int n_in,
                              void* d_out, int out_size) {
    const float* x     = (const float*)d_in[0];
    const int*   ei    = (const int*)d_in[1];
    const int*   batch = (const int*)d_in[2];
    const float* W1 = (const float*)d_in[3];
    const float* b1 = (const float*)d_in[4];
    const float* W2 = (const float*)d_in[5];
    const float* b2 = (const float*)d_in[6];
    const float* W3 = (const float*)d_in[7];
    const float* b3 = (const float*)d_in[8];
    const float* W4 = (const float*)d_in[9];
    const float* b4 = (const float*)d_in[10];
    const float* W5 = (const float*)d_in[11];
    const float* b5 = (const float*)d_in[12];
    const float* Wout = (const float*)d_in[13];
    const float* bout = (const float*)d_in[14];
    float* out = (float*)d_out;

    static bool attr_set = false;
    if (!attr_set) {
        cudaFuncSetAttribute(gemm_kernel<Ff, true>,
                             cudaFuncAttributeMaxDynamicSharedMemorySize, GSMEM_BYTES);
        cudaFuncSetAttribute(gemm_kernel<Hh, false>,
                             cudaFuncAttributeMaxDynamicSharedMemorySize, GSMEM_BYTES);
        attr_set = true;
    }

    const int PREP_N = Ee + Nn + Ff * Hh + 4 * Hh * Hh;
    const int SCAT_N = Ee + (Nn * Ff) / 2;
    dim3 ggrid(Hh / 128, (Nn + 127) / 128);   // (2, 157)

    pdl_launch(prep_kernel, dim3((PREP_N + 255) / 256), dim3(256), 0,
               ei, batch, W1, W2, W3, W4, W5);
    pdl_launch(scan_kernel, dim3(1), dim3(SCAN_T), 0);
    pdl_launch(scatter_kernel, dim3((SCAT_N + 255) / 256), dim3(256), 0, ei, x);

    // layer 1: aggregate x first (A(XW) = (AX)W), then GEMM with bias+relu
    pdl_launch(aggx_kernel, dim3(Nn / 8), dim3(256), 0);
    pdl_launch(gemm_kernel<Ff, true>, ggrid, dim3(256), (size_t)GSMEM_BYTES, 0, b1);

    // layers 2..5  (agg uses 4 warps/node -> Nn/2 blocks)
    pdl_launch(gemm_kernel<Hh, false>, ggrid, dim3(256), (size_t)GSMEM_BYTES, 0, (const float*)nullptr);
    pdl_launch(agg_kernel<false>, dim3(Nn / 2), dim3(256), 0, b2, batch);
    pdl_launch(gemm_kernel<Hh, false>, ggrid, dim3(256), (size_t)GSMEM_BYTES, 1, (const float*)nullptr);
    pdl_launch(agg_kernel<false>, dim3(Nn / 2), dim3(256), 0, b3, batch);
    pdl_launch(gemm_kernel<Hh, false>, ggrid, dim3(256), (size_t)GSMEM_BYTES, 2, (const float*)nullptr);
    pdl_launch(agg_kernel<false>, dim3(Nn / 2), dim3(256), 0, b4, batch);
    pdl_launch(gemm_kernel<Hh, false>, ggrid, dim3(256), (size_t)GSMEM_BYTES, 3, (const float*)nullptr);
    pdl_launch(agg_kernel<true>, dim3(Nn / 2), dim3(256), 0, b5, batch);   // fused pool

    pdl_launch(out_kernel, dim3(Gg), dim3(256), 0, Wout, bout, out);
}